// round 5
// baseline (speedup 1.0000x reference)
#include <cuda_runtime.h>
#include <cstdint>
#include <cstddef>
#include <math_constants.h>

#define BB 4
#define NN 4096
#define CC 64
#define KK 16
#define QW 32            // query-warps per knn block (1024 threads)
#define WPB 8            // warps per mlp block
#define TPB (WPB*32)

// scratch (static device globals: no allocation allowed)
__device__ int g_knn[BB*NN*KK];

// ---- packed f32x2 helpers (FFMA2: only reachable via PTX fma.rn.f32x2) ----
__device__ __forceinline__ unsigned long long pack2(float lo, float hi){
  unsigned long long v;
  asm("mov.b64 %0, {%1,%2};" : "=l"(v) : "f"(lo), "f"(hi));
  return v;
}
__device__ __forceinline__ void unpack2(unsigned long long v, float &lo, float &hi){
  asm("mov.b64 {%0,%1}, %2;" : "=f"(lo), "=f"(hi) : "l"(v));
}
__device__ __forceinline__ unsigned long long ffma2(unsigned long long a,
                                                    unsigned long long b,
                                                    unsigned long long c){
  unsigned long long d;
  asm("fma.rn.f32x2 %0, %1, %2, %3;" : "=l"(d) : "l"(a), "l"(b), "l"(c));
  return d;
}

// ============================================================================
// Kernel 1: warp-per-query exact 16-NN.
// smem holds (x,y,z,|p|^2) per point; d = |q|^2 + |p|^2 - 2 q.p
// -> hot loop = 1 LDS.128 + 1 FADD + 3 FMA + ballot.
// Lanes 0..15 hold the distributed top-16; warp-shared threshold 'worst'.
// ============================================================================
__global__ __launch_bounds__(QW*32) void knn_warp(const float* __restrict__ xyz){
  extern __shared__ float4 s4[];               // 64KB
  const int b = blockIdx.y;
  const float* base = xyz + (size_t)b * NN * 3;
  const int tid = threadIdx.x;
  for (int i = tid; i < NN; i += QW*32){
    float px = base[3*i], py = base[3*i+1], pz = base[3*i+2];
    s4[i] = make_float4(px, py, pz, fmaf(px, px, fmaf(py, py, pz*pz)));
  }
  __syncthreads();

  const int wid = tid >> 5, lane = tid & 31;
  const int q = blockIdx.x * QW + wid;
  const float4 qp = s4[q];
  const float nqx = -2.f*qp.x, nqy = -2.f*qp.y, nqz = -2.f*qp.z, qq = qp.w;

  // warm-start: lanes 0..15 seeded with points 0..15 (self -> +inf)
  float myD = CUDART_INF_F; int myIdx = 0;
  if (lane < KK){
    float4 p4 = s4[lane];
    float d = fmaf(nqx, p4.x, fmaf(nqy, p4.y, fmaf(nqz, p4.z, qq + p4.w)));
    myD = (lane == q) ? CUDART_INF_F : d;
    myIdx = lane;
  }
  float w = (lane < KK) ? myD : -CUDART_INF_F;
  #pragma unroll
  for (int x = 16; x; x >>= 1) w = fmaxf(w, __shfl_xor_sync(0xffffffffu, w, x));
  float worst = w;

  for (int j0 = KK; j0 < NN; j0 += 32){
    int j = j0 + lane;
    int jc = (j < NN) ? j : (NN - 1);
    float4 p4 = s4[jc];
    float d = fmaf(nqx, p4.x, fmaf(nqy, p4.y, fmaf(nqz, p4.z, qq + p4.w)));
    bool hit = (d < worst) && (j != q) && (j < NN);
    unsigned m = __ballot_sync(0xffffffffu, hit);
    while (m){
      int src = __ffs(m) - 1; m &= m - 1;
      float cd = __shfl_sync(0xffffffffu, d, src);
      if (cd < worst){                       // warp-uniform recheck
        unsigned em = __ballot_sync(0xffffffffu, (lane < KK) && (myD == worst));
        int leader = __ffs(em) - 1;
        if (lane == leader){ myD = cd; myIdx = j0 + src; }
        float v = (lane < KK) ? myD : -CUDART_INF_F;
        #pragma unroll
        for (int x = 16; x; x >>= 1) v = fmaxf(v, __shfl_xor_sync(0xffffffffu, v, x));
        worst = v;
      }
    }
  }
  if (lane < KK) g_knn[((size_t)b * NN + q) * KK + lane] = myIdx;
}

// ============================================================================
// Kernel 2: register-resident MLP. Lane = one neighbor; warp = 2 points
// (lanes 0-15 -> point A, 16-31 -> point B). h[64] and acc[32] (f32x2 over
// channel pairs) live in registers; only LDS is broadcast weight reads.
// Max-pool = shfl butterfly over the 16-lane group; lane nb==0 stores.
// ============================================================================
__global__ __launch_bounds__(TPB) void mlp_kernel(
    const float* __restrict__ xyz,
    const float* __restrict__ w1,
    const float* __restrict__ w2,
    const float* __restrict__ w3,
    float* __restrict__ out)
{
  __shared__ float w1s4[CC*4];     // padded (a,b,g,0) per channel
  __shared__ float w2T[CC*CC];     // w2T[c_in*64 + c_out]
  __shared__ float w3T[CC*CC];

  const int tid = threadIdx.x, wid = tid >> 5, lane = tid & 31;
  const int half = lane >> 4, nb = lane & 15;

  for (int t = tid; t < CC*4; t += TPB){
    int c = t >> 2, e = t & 3;
    w1s4[t] = (e < 3) ? w1[c*3 + e] : 0.f;
  }
  for (int t = tid; t < CC*CC; t += TPB){
    int o = t >> 6, c = t & 63;
    w2T[c*64 + o] = w2[t];
    w3T[c*64 + o] = w3[t];
  }
  __syncthreads();

  const int point = blockIdx.x * (WPB*2) + wid*2 + half;   // 0..BB*NN-1
  const int b = point >> 12;
  const int n = point & (NN - 1);
  const float* xb = xyz + (size_t)b * NN * 3;

  // gather relative coords for this lane's neighbor
  const int ng = g_knn[(size_t)point * KK + nb];
  const float rx = xb[ng*3+0] - xb[n*3+0];
  const float ry = xb[ng*3+1] - xb[n*3+1];
  const float rz = xb[ng*3+2] - xb[n*3+2];

  float h[CC];
  unsigned long long acc[32];

  // ---- layer 1 (regs) ----
  {
    const float4* w1v = reinterpret_cast<const float4*>(w1s4);
    #pragma unroll
    for (int c = 0; c < CC; c++){
      float4 wv = w1v[c];
      h[c] = fmaxf(fmaf(wv.x, rx, fmaf(wv.y, ry, wv.z*rz)), 0.f);
    }
  }

  // ---- layer 2: acc[t] = (out[2t], out[2t+1]) over c' pairs ----
  #pragma unroll
  for (int t = 0; t < 32; t++) acc[t] = 0ull;
  {
    const ulonglong2* wp = reinterpret_cast<const ulonglong2*>(w2T);
    #pragma unroll
    for (int c = 0; c < CC; c++){
      unsigned long long hp = pack2(h[c], h[c]);
      #pragma unroll
      for (int t = 0; t < 16; t++){
        ulonglong2 wv = wp[c*16 + t];
        acc[2*t]   = ffma2(wv.x, hp, acc[2*t]);
        acc[2*t+1] = ffma2(wv.y, hp, acc[2*t+1]);
      }
    }
  }
  #pragma unroll
  for (int t = 0; t < 32; t++){
    float lo, hi; unpack2(acc[t], lo, hi);
    h[2*t] = fmaxf(lo, 0.f); h[2*t+1] = fmaxf(hi, 0.f);
    acc[t] = 0ull;
  }

  // ---- layer 3 (no relu) ----
  {
    const ulonglong2* wp = reinterpret_cast<const ulonglong2*>(w3T);
    #pragma unroll
    for (int c = 0; c < CC; c++){
      unsigned long long hp = pack2(h[c], h[c]);
      #pragma unroll
      for (int t = 0; t < 16; t++){
        ulonglong2 wv = wp[c*16 + t];
        acc[2*t]   = ffma2(wv.x, hp, acc[2*t]);
        acc[2*t+1] = ffma2(wv.y, hp, acc[2*t+1]);
      }
    }
  }

  // ---- max-pool over neighbors: butterfly within the 16-lane group ----
  float m[CC];
  #pragma unroll
  for (int t = 0; t < 32; t++) unpack2(acc[t], m[2*t], m[2*t+1]);
  #pragma unroll
  for (int d = 1; d < 16; d <<= 1){
    #pragma unroll
    for (int c = 0; c < CC; c++)
      m[c] = fmaxf(m[c], __shfl_xor_sync(0xffffffffu, m[c], d));
  }

  if (nb == 0){
    float* ob = out + ((size_t)b * CC) * NN + n;
    #pragma unroll
    for (int c = 0; c < CC; c++) ob[(size_t)c * NN] = m[c];
  }
}

// ============================================================================
extern "C" void kernel_launch(void* const* d_in, const int* in_sizes, int n_in,
                              void* d_out, int out_size)
{
  const float* xyz = (const float*)d_in[0];
  const float* w1  = (const float*)d_in[1];
  const float* w2  = (const float*)d_in[2];
  const float* w3  = (const float*)d_in[3];
  float* out = (float*)d_out;
  (void)in_sizes; (void)n_in; (void)out_size;

  size_t ksmem = (size_t)NN * sizeof(float4);   // 64KB
  cudaFuncSetAttribute(knn_warp, cudaFuncAttributeMaxDynamicSharedMemorySize, (int)ksmem);
  knn_warp<<<dim3(NN/QW, BB), QW*32, ksmem>>>(xyz);

  mlp_kernel<<<(BB*NN)/(WPB*2), TPB>>>(xyz, w1, w2, w3, out);
}

// round 7
// speedup vs baseline: 1.2267x; 1.2267x over previous
#include <cuda_runtime.h>
#include <cstdint>
#include <cstddef>
#include <math_constants.h>

#define BB 4
#define NN 4096
#define CC 64
#define KK 16
#define KQW 16           // warps per knn block (512 threads, 2 queries/warp)
#define MW 8             // warps per mlp block
#define MT (MW*32)

// scratch (static device globals: no allocation allowed)
__device__ int g_knn[BB*NN*KK];

// ---- packed f32x2 helpers (FFMA2: only reachable via PTX fma.rn.f32x2) ----
__device__ __forceinline__ unsigned long long pack2(float lo, float hi){
  unsigned long long v;
  asm("mov.b64 %0, {%1,%2};" : "=l"(v) : "f"(lo), "f"(hi));
  return v;
}
__device__ __forceinline__ void unpack2(unsigned long long v, float &lo, float &hi){
  asm("mov.b64 {%0,%1}, %2;" : "=f"(lo), "=f"(hi) : "l"(v));
}
__device__ __forceinline__ unsigned long long ffma2(unsigned long long a,
                                                    unsigned long long b,
                                                    unsigned long long c){
  unsigned long long d;
  asm("fma.rn.f32x2 %0, %1, %2, %3;" : "=l"(d) : "l"(a), "l"(b), "l"(c));
  return d;
}
__device__ __forceinline__ unsigned long long relu2(unsigned long long v){
  float lo, hi; unpack2(v, lo, hi);
  return pack2(fmaxf(lo, 0.f), fmaxf(hi, 0.f));
}
__device__ __forceinline__ float qmax(ulonglong2 v){
  float a, b, c, d;
  unpack2(v.x, a, b); unpack2(v.y, c, d);
  return fmaxf(fmaxf(a, b), fmaxf(c, d));
}

// ============================================================================
// Kernel 1: warp-per-2-queries exact 16-NN.
// smem: (x,y,z,|p|^2) per point; d = |q|^2+|p|^2-2q.p -> 1 LDS.128 feeds both
// queries. Lanes 0..15 hold distributed top-16 per query; warp-shared worst.
// ============================================================================
__device__ __forceinline__ void insert_hits(unsigned m, float d, int j0,
                                            float& myD, int& myI, float& worst,
                                            int lane){
  while (m){
    int src = __ffs(m) - 1; m &= m - 1;
    float cd = __shfl_sync(0xffffffffu, d, src);
    if (cd < worst){
      unsigned em = __ballot_sync(0xffffffffu, (lane < KK) && (myD == worst));
      int leader = __ffs(em) - 1;
      if (lane == leader){ myD = cd; myI = j0 + src; }
      float v = (lane < KK) ? myD : -CUDART_INF_F;
      #pragma unroll
      for (int x = 8; x; x >>= 1) v = fmaxf(v, __shfl_xor_sync(0xffffffffu, v, x));
      worst = __shfl_sync(0xffffffffu, v, 0);
    }
  }
}

__global__ __launch_bounds__(KQW*32) void knn_warp(const float* __restrict__ xyz){
  extern __shared__ float4 s4[];               // 64KB: full point DB of one batch
  const int b = blockIdx.y;
  const float* base = xyz + (size_t)b * NN * 3;
  const int tid = threadIdx.x;
  for (int i = tid; i < NN; i += KQW*32){
    float px = base[3*i], py = base[3*i+1], pz = base[3*i+2];
    s4[i] = make_float4(px, py, pz, fmaf(px, px, fmaf(py, py, pz*pz)));
  }
  __syncthreads();

  const int wid = tid >> 5, lane = tid & 31;
  const int q0 = blockIdx.x * (2*KQW) + 2*wid;
  const int q1 = q0 + 1;
  const float4 qa = s4[q0], qb = s4[q1];
  const float n0x = -2.f*qa.x, n0y = -2.f*qa.y, n0z = -2.f*qa.z, qq0 = qa.w;
  const float n1x = -2.f*qb.x, n1y = -2.f*qb.y, n1z = -2.f*qb.z, qq1 = qb.w;

  // seed lanes 0..15 with points 0..15
  float myD0 = CUDART_INF_F, myD1 = CUDART_INF_F;
  int myI0 = 0, myI1 = 0;
  if (lane < KK){
    float4 p = s4[lane];
    float d0 = fmaf(n0x, p.x, fmaf(n0y, p.y, fmaf(n0z, p.z, qq0 + p.w)));
    float d1 = fmaf(n1x, p.x, fmaf(n1y, p.y, fmaf(n1z, p.z, qq1 + p.w)));
    myD0 = (lane == q0) ? CUDART_INF_F : d0;
    myD1 = (lane == q1) ? CUDART_INF_F : d1;
    myI0 = myI1 = lane;
  }
  float v0 = (lane < KK) ? myD0 : -CUDART_INF_F;
  float v1 = (lane < KK) ? myD1 : -CUDART_INF_F;
  #pragma unroll
  for (int x = 8; x; x >>= 1){
    v0 = fmaxf(v0, __shfl_xor_sync(0xffffffffu, v0, x));
    v1 = fmaxf(v1, __shfl_xor_sync(0xffffffffu, v1, x));
  }
  float worst0 = __shfl_sync(0xffffffffu, v0, 0);
  float worst1 = __shfl_sync(0xffffffffu, v1, 0);

  // peeled first block: points 16..31 handled by upper 16 lanes (j = lane + 16
  // would double-visit seeds; instead visit j = lane with mask lane >= 16)
  {
    const int j = lane;
    float4 p = s4[j];
    float d0 = fmaf(n0x, p.x, fmaf(n0y, p.y, fmaf(n0z, p.z, qq0 + p.w)));
    float d1 = fmaf(n1x, p.x, fmaf(n1y, p.y, fmaf(n1z, p.z, qq1 + p.w)));
    bool live = (lane >= KK);
    unsigned m0 = __ballot_sync(0xffffffffu, live && (d0 < worst0) && (j != q0));
    unsigned m1 = __ballot_sync(0xffffffffu, live && (d1 < worst1) && (j != q1));
    if (m0) insert_hits(m0, d0, 0, myD0, myI0, worst0, lane);
    if (m1) insert_hits(m1, d1, 0, myD1, myI1, worst1, lane);
  }

  for (int j0i = 32; j0i < NN; j0i += 32){    // 32-aligned: j max = NN-1, in-bounds
    const int j = j0i + lane;
    float4 p = s4[j];
    float d0 = fmaf(n0x, p.x, fmaf(n0y, p.y, fmaf(n0z, p.z, qq0 + p.w)));
    float d1 = fmaf(n1x, p.x, fmaf(n1y, p.y, fmaf(n1z, p.z, qq1 + p.w)));
    unsigned m0 = __ballot_sync(0xffffffffu, (d0 < worst0) && (j != q0));
    unsigned m1 = __ballot_sync(0xffffffffu, (d1 < worst1) && (j != q1));
    if (m0) insert_hits(m0, d0, j0i, myD0, myI0, worst0, lane);
    if (m1) insert_hits(m1, d1, j0i, myD1, myI1, worst1, lane);
  }
  if (lane < KK){
    g_knn[((size_t)b * NN + q0) * KK + lane] = myI0;
    g_knn[((size_t)b * NN + q1) * KK + lane] = myI1;
  }
}

// ============================================================================
// Kernel 2: m-tiled register GEMM MLP.
// Warp tile: m=32 (2 points x 16 neighbors), lane owns out channels
// (lane, lane+32). h tile [64 x 32] in per-warp smem, chunk-rotated
// ((chunk + row) & 7) for conflict-free stores and 16B broadcast loads.
// Weights in smem with per-row XOR swizzle (coalesced fill + reads).
// Inner step j: 2 coalesced LDS.32 (weights) + 8 x LDS.128 broadcast (h row)
// + 32 ffma2 -> fma-pipe bound.
// ============================================================================
__device__ __forceinline__ void gemm_layer(const float* __restrict__ wT,
                                           const float* __restrict__ h,
                                           int lane, ulonglong2* A, ulonglong2* B){
  #pragma unroll
  for (int c = 0; c < 8; c++){
    A[c].x = 0ull; A[c].y = 0ull; B[c].x = 0ull; B[c].y = 0ull;
  }
  #pragma unroll 2
  for (int j8 = 0; j8 < 8; j8++){
    #pragma unroll
    for (int jj = 0; jj < 8; jj++){
      const int j = j8*8 + jj;
      const int jx = j & 31;
      float wa0 = wT[j*64 + (lane ^ jx)];
      float wb0 = wT[j*64 + 32 + (lane ^ jx)];
      unsigned long long wa = pack2(wa0, wa0);
      unsigned long long wb = pack2(wb0, wb0);
      const ulonglong2* hrow = reinterpret_cast<const ulonglong2*>(h + j*32);
      #pragma unroll
      for (int c = 0; c < 8; c++){
        ulonglong2 hv = hrow[(c + jj) & 7];    // compile-time rotation
        A[c].x = ffma2(wa, hv.x, A[c].x);
        A[c].y = ffma2(wa, hv.y, A[c].y);
        B[c].x = ffma2(wb, hv.x, B[c].x);
        B[c].y = ffma2(wb, hv.y, B[c].y);
      }
    }
  }
}

__global__ __launch_bounds__(MT, 2) void mlp_kernel(
    const float* __restrict__ xyz,
    const float* __restrict__ w1,
    const float* __restrict__ w2,
    const float* __restrict__ w3,
    float* __restrict__ out)
{
  extern __shared__ float sm[];
  float* w1s = sm;              // 256  (64 x (a,b,g,0))
  float* w2T = sm + 256;        // 4096 swizzled [c_in][c_out ^ (c_in&31)]
  float* w3T = w2T + 4096;      // 4096
  float* hb  = w3T + 4096;      // MW * 2048

  const int tid = threadIdx.x, wid = tid >> 5, lane = tid & 31;

  for (int t = tid; t < 256; t += MT){
    int c = t >> 2, e = t & 3;
    w1s[t] = (e < 3) ? w1[c*3 + e] : 0.f;
  }
  for (int t = tid; t < 4096; t += MT){
    int o = t >> 6, c = t & 63;
    int phys = c*64 + (o ^ (c & 31));
    w2T[phys] = w2[t];
    w3T[phys] = w3[t];
  }
  __syncthreads();

  float* h = hb + wid * 2048;
  const int pt0 = blockIdx.x * (MW*2) + wid*2;   // 2 points per warp
  const int mpt = lane >> 4;                      // which of the 2 points
  const int nb  = lane & 15;                      // neighbor id
  const int point = pt0 + mpt;
  const int b = pt0 >> 12;                        // pair never straddles batch
  const int nA = pt0 & (NN-1), nB = nA + 1;
  const float* xb = xyz + (size_t)b * NN * 3;
  const int n = point & (NN-1);

  const int ng = g_knn[(size_t)point * KK + nb];
  const float rx = xb[ng*3+0] - xb[n*3+0];
  const float ry = xb[ng*3+1] - xb[n*3+1];
  const float rz = xb[ng*3+2] - xb[n*3+2];

  // ---- layer 1: h[c][m=lane] (rotated chunk layout), conflict-free STS.32 ----
  {
    const int mc = lane >> 2, ml = lane & 3;
    const float4* w1v = reinterpret_cast<const float4*>(w1s);
    #pragma unroll 8
    for (int c = 0; c < CC; c++){
      float4 wv = w1v[c];
      float v = fmaxf(fmaf(wv.x, rx, fmaf(wv.y, ry, wv.z*rz)), 0.f);
      h[c*32 + (((mc + c) & 7) << 2) + ml] = v;
    }
  }
  __syncwarp();

  ulonglong2 A[8], Bacc[8];

  // ---- layer 2 ----
  gemm_layer(w2T, h, lane, A, Bacc);
  __syncwarp();                 // all reads of h done before overwrite
  #pragma unroll
  for (int c = 0; c < 8; c++){
    ulonglong2 va; va.x = relu2(A[c].x);    va.y = relu2(A[c].y);
    ulonglong2 vb; vb.x = relu2(Bacc[c].x); vb.y = relu2(Bacc[c].y);
    const int pc = ((c + lane) & 7) << 2;   // same rotation, rows lane / lane+32
    *reinterpret_cast<ulonglong2*>(h + lane*32 + pc)      = va;
    *reinterpret_cast<ulonglong2*>(h + (lane+32)*32 + pc) = vb;
  }
  __syncwarp();

  // ---- layer 3 + fused max-pool over neighbors ----
  gemm_layer(w3T, h, lane, A, Bacc);

  float a0 = -CUDART_INF_F, a1 = -CUDART_INF_F;   // o=lane:    ptA, ptB
  float b0 = -CUDART_INF_F, b1 = -CUDART_INF_F;   // o=lane+32: ptA, ptB
  #pragma unroll
  for (int c = 0; c < 4; c++){
    a0 = fmaxf(a0, qmax(A[c]));    b0 = fmaxf(b0, qmax(Bacc[c]));
    a1 = fmaxf(a1, qmax(A[c+4]));  b1 = fmaxf(b1, qmax(Bacc[c+4]));
  }
  out[((size_t)b*CC + lane)      * NN + nA] = a0;
  out[((size_t)b*CC + lane)      * NN + nB] = a1;
  out[((size_t)b*CC + lane + 32) * NN + nA] = b0;
  out[((size_t)b*CC + lane + 32) * NN + nB] = b1;
}

// ============================================================================
extern "C" void kernel_launch(void* const* d_in, const int* in_sizes, int n_in,
                              void* d_out, int out_size)
{
  const float* xyz = (const float*)d_in[0];
  const float* w1  = (const float*)d_in[1];
  const float* w2  = (const float*)d_in[2];
  const float* w3  = (const float*)d_in[3];
  float* out = (float*)d_out;
  (void)in_sizes; (void)n_in; (void)out_size;

  size_t ksmem = (size_t)NN * sizeof(float4);   // 64KB
  cudaFuncSetAttribute(knn_warp, cudaFuncAttributeMaxDynamicSharedMemorySize, (int)ksmem);
  knn_warp<<<dim3(NN/(2*KQW), BB), KQW*32, ksmem>>>(xyz);

  size_t msmem = (size_t)(256 + 4096 + 4096 + MW*2048) * sizeof(float); // 99328 B
  cudaFuncSetAttribute(mlp_kernel, cudaFuncAttributeMaxDynamicSharedMemorySize, (int)msmem);
  mlp_kernel<<<(BB*NN)/(MW*2), MT, msmem>>>(xyz, w1, w2, w3, out);
}

// round 8
// speedup vs baseline: 1.3635x; 1.1115x over previous
#include <cuda_runtime.h>
#include <cstdint>
#include <cstddef>
#include <math_constants.h>

#define BB 4
#define NN 4096
#define CC 64
#define KK 16
#define KWPB 16          // warps per knn block (512 threads, 4 queries/warp)
#define QPW 4            // queries per warp
#define MW 8             // warps per mlp block
#define MT (MW*32)

// scratch (static device globals: no allocation allowed)
__device__ int g_knn[BB*NN*KK];

// ---- packed f32x2 helpers (FFMA2: only reachable via PTX fma.rn.f32x2) ----
__device__ __forceinline__ unsigned long long pack2(float lo, float hi){
  unsigned long long v;
  asm("mov.b64 %0, {%1,%2};" : "=l"(v) : "f"(lo), "f"(hi));
  return v;
}
__device__ __forceinline__ void unpack2(unsigned long long v, float &lo, float &hi){
  asm("mov.b64 {%0,%1}, %2;" : "=f"(lo), "=f"(hi) : "l"(v));
}
__device__ __forceinline__ unsigned long long ffma2(unsigned long long a,
                                                    unsigned long long b,
                                                    unsigned long long c){
  unsigned long long d;
  asm("fma.rn.f32x2 %0, %1, %2, %3;" : "=l"(d) : "l"(a), "l"(b), "l"(c));
  return d;
}
__device__ __forceinline__ unsigned long long relu2(unsigned long long v){
  float lo, hi; unpack2(v, lo, hi);
  return pack2(fmaxf(lo, 0.f), fmaxf(hi, 0.f));
}
__device__ __forceinline__ float qmax(ulonglong2 v){
  float a, b, c, d;
  unpack2(v.x, a, b); unpack2(v.y, c, d);
  return fmaxf(fmaxf(a, b), fmaxf(c, d));
}

// ============================================================================
// Kernel 1: warp-per-4-queries exact 16-NN.
// smem: (x,y,z,|p|^2) per point; d = |q|^2+|p|^2-2q.p -> 1 LDS.128 feeds 4
// queries. Lanes 0..15 hold distributed top-16 per query; warp-shared worst
// maintained with a single REDUX.MAX.U32 (squared distances are >= 0, so
// uint-bit order == float order).
// ============================================================================
__device__ __forceinline__ void insert_hits(unsigned m, float d, int j0,
                                            float& myD, int& myI, float& worst,
                                            int lane){
  while (m){
    int src = __ffs(m) - 1; m &= m - 1;
    float cd = __shfl_sync(0xffffffffu, d, src);
    if (cd < worst){                                   // warp-uniform
      unsigned em = __ballot_sync(0xffffffffu, (lane < KK) && (myD == worst));
      int leader = __ffs(em) - 1;
      if (lane == leader){ myD = cd; myI = j0 + src; }
      unsigned u = (lane < KK) ? __float_as_uint(myD) : 0u;
      worst = __uint_as_float(__reduce_max_sync(0xffffffffu, u));
    }
  }
}

__global__ __launch_bounds__(KWPB*32) void knn_warp(const float* __restrict__ xyz){
  extern __shared__ float4 s4[];               // 64KB: full point DB of one batch
  const int b = blockIdx.y;
  const float* base = xyz + (size_t)b * NN * 3;
  const int tid = threadIdx.x;
  for (int i = tid; i < NN; i += KWPB*32){
    float px = base[3*i], py = base[3*i+1], pz = base[3*i+2];
    s4[i] = make_float4(px, py, pz, fmaf(px, px, fmaf(py, py, pz*pz)));
  }
  __syncthreads();

  const int wid = tid >> 5, lane = tid & 31;
  const int qbase = (blockIdx.x * KWPB + wid) * QPW;
  const unsigned qblk = (unsigned)qbase & ~31u;        // 32-block containing all 4 q's

  float4 qv[QPW];
  #pragma unroll
  for (int k = 0; k < QPW; k++) qv[k] = s4[qbase + k];
  float nx[QPW], ny[QPW], nz[QPW], qq[QPW];
  #pragma unroll
  for (int k = 0; k < QPW; k++){
    nx[k] = -2.f*qv[k].x; ny[k] = -2.f*qv[k].y; nz[k] = -2.f*qv[k].z; qq[k] = qv[k].w;
  }

  // seeds: lanes 0..15 take points 0..15 (self -> +inf)
  float myD[QPW]; int myI[QPW]; float worst[QPW];
  #pragma unroll
  for (int k = 0; k < QPW; k++){ myD[k] = CUDART_INF_F; myI[k] = 0; }
  if (lane < KK){
    float4 p = s4[lane];
    #pragma unroll
    for (int k = 0; k < QPW; k++){
      float d = fmaf(nx[k], p.x, fmaf(ny[k], p.y, fmaf(nz[k], p.z, qq[k] + p.w)));
      myD[k] = (lane == qbase + k) ? CUDART_INF_F : d;
      myI[k] = lane;
    }
  }
  #pragma unroll
  for (int k = 0; k < QPW; k++){
    unsigned u = (lane < KK) ? __float_as_uint(myD[k]) : 0u;
    worst[k] = __uint_as_float(__reduce_max_sync(0xffffffffu, u));
  }

  // peeled block: points 16..31 via upper lanes (explicit self check, once)
  {
    float4 p = s4[lane];
    bool live = (lane >= KK);
    #pragma unroll
    for (int k = 0; k < QPW; k++){
      float d = fmaf(nx[k], p.x, fmaf(ny[k], p.y, fmaf(nz[k], p.z, qq[k] + p.w)));
      unsigned m = __ballot_sync(0xffffffffu,
                                 live && (d < worst[k]) && (lane != qbase + k));
      if (m) insert_hits(m, d, 0, myD[k], myI[k], worst[k], lane);
    }
  }

  #pragma unroll 2
  for (int j0i = 32; j0i < NN; j0i += 32){
    const int j = j0i + lane;
    float4 p = s4[j];
    float d[QPW]; unsigned m[QPW];
    #pragma unroll
    for (int k = 0; k < QPW; k++){
      d[k] = fmaf(nx[k], p.x, fmaf(ny[k], p.y, fmaf(nz[k], p.z, qq[k] + p.w)));
      m[k] = __ballot_sync(0xffffffffu, d[k] < worst[k]);
    }
    if ((unsigned)j0i == qblk){                 // clear self bits (one iteration)
      #pragma unroll
      for (int k = 0; k < QPW; k++) m[k] &= ~(1u << ((qbase + k) - j0i));
    }
    #pragma unroll
    for (int k = 0; k < QPW; k++)
      if (m[k]) insert_hits(m[k], d[k], j0i, myD[k], myI[k], worst[k], lane);
  }

  if (lane < KK){
    #pragma unroll
    for (int k = 0; k < QPW; k++)
      g_knn[((size_t)b * NN + qbase + k) * KK + lane] = myI[k];
  }
}

// ============================================================================
// Kernel 2: m-tiled register GEMM MLP (structure unchanged from R7; gather
// hoisted above smem staging to overlap LDG latency with the fill).
// ============================================================================
__device__ __forceinline__ void gemm_layer(const float* __restrict__ wT,
                                           const float* __restrict__ h,
                                           int lane, ulonglong2* A, ulonglong2* B){
  #pragma unroll
  for (int c = 0; c < 8; c++){
    A[c].x = 0ull; A[c].y = 0ull; B[c].x = 0ull; B[c].y = 0ull;
  }
  #pragma unroll 2
  for (int j8 = 0; j8 < 8; j8++){
    #pragma unroll
    for (int jj = 0; jj < 8; jj++){
      const int j = j8*8 + jj;
      const int jx = j & 31;
      float wa0 = wT[j*64 + (lane ^ jx)];
      float wb0 = wT[j*64 + 32 + (lane ^ jx)];
      unsigned long long wa = pack2(wa0, wa0);
      unsigned long long wb = pack2(wb0, wb0);
      const ulonglong2* hrow = reinterpret_cast<const ulonglong2*>(h + j*32);
      #pragma unroll
      for (int c = 0; c < 8; c++){
        ulonglong2 hv = hrow[(c + jj) & 7];    // compile-time rotation
        A[c].x = ffma2(wa, hv.x, A[c].x);
        A[c].y = ffma2(wa, hv.y, A[c].y);
        B[c].x = ffma2(wb, hv.x, B[c].x);
        B[c].y = ffma2(wb, hv.y, B[c].y);
      }
    }
  }
}

__global__ __launch_bounds__(MT, 2) void mlp_kernel(
    const float* __restrict__ xyz,
    const float* __restrict__ w1,
    const float* __restrict__ w2,
    const float* __restrict__ w3,
    float* __restrict__ out)
{
  extern __shared__ float sm[];
  float* w1s = sm;              // 256  (64 x (a,b,g,0))
  float* w2T = sm + 256;        // 4096 swizzled [c_in][c_out ^ (c_in&31)]
  float* w3T = w2T + 4096;      // 4096
  float* hb  = w3T + 4096;      // MW * 2048

  const int tid = threadIdx.x, wid = tid >> 5, lane = tid & 31;

  // -- hoisted gather: issue global loads before smem staging --
  const int pt0 = blockIdx.x * (MW*2) + wid*2;   // 2 points per warp
  const int mpt = lane >> 4;                      // which of the 2 points
  const int nb  = lane & 15;                      // neighbor id
  const int point = pt0 + mpt;
  const int b = pt0 >> 12;                        // pair never straddles batch
  const int nA = pt0 & (NN-1), nB = nA + 1;
  const float* xb = xyz + (size_t)b * NN * 3;
  const int n = point & (NN-1);

  const int ng = g_knn[(size_t)point * KK + nb];
  const float rx = xb[ng*3+0] - xb[n*3+0];
  const float ry = xb[ng*3+1] - xb[n*3+1];
  const float rz = xb[ng*3+2] - xb[n*3+2];

  for (int t = tid; t < 256; t += MT){
    int c = t >> 2, e = t & 3;
    w1s[t] = (e < 3) ? w1[c*3 + e] : 0.f;
  }
  for (int t = tid; t < 4096; t += MT){
    int o = t >> 6, c = t & 63;
    int phys = c*64 + (o ^ (c & 31));
    w2T[phys] = w2[t];
    w3T[phys] = w3[t];
  }
  __syncthreads();

  float* h = hb + wid * 2048;

  // ---- layer 1: h[c][m=lane] (rotated chunk layout), conflict-free stores ----
  {
    const int mc = lane >> 2, ml = lane & 3;
    const float4* w1v = reinterpret_cast<const float4*>(w1s);
    #pragma unroll 8
    for (int c = 0; c < CC; c++){
      float4 wv = w1v[c];
      float v = fmaxf(fmaf(wv.x, rx, fmaf(wv.y, ry, wv.z*rz)), 0.f);
      h[c*32 + (((mc + c) & 7) << 2) + ml] = v;
    }
  }
  __syncwarp();

  ulonglong2 A[8], Bacc[8];

  // ---- layer 2 ----
  gemm_layer(w2T, h, lane, A, Bacc);
  __syncwarp();                 // all reads of h done before overwrite
  #pragma unroll
  for (int c = 0; c < 8; c++){
    ulonglong2 va; va.x = relu2(A[c].x);    va.y = relu2(A[c].y);
    ulonglong2 vb; vb.x = relu2(Bacc[c].x); vb.y = relu2(Bacc[c].y);
    const int pc = ((c + lane) & 7) << 2;   // same rotation, rows lane / lane+32
    *reinterpret_cast<ulonglong2*>(h + lane*32 + pc)      = va;
    *reinterpret_cast<ulonglong2*>(h + (lane+32)*32 + pc) = vb;
  }
  __syncwarp();

  // ---- layer 3 + fused max-pool over neighbors ----
  gemm_layer(w3T, h, lane, A, Bacc);

  float a0 = -CUDART_INF_F, a1 = -CUDART_INF_F;   // o=lane:    ptA, ptB
  float b0 = -CUDART_INF_F, b1 = -CUDART_INF_F;   // o=lane+32: ptA, ptB
  #pragma unroll
  for (int c = 0; c < 4; c++){
    a0 = fmaxf(a0, qmax(A[c]));    b0 = fmaxf(b0, qmax(Bacc[c]));
    a1 = fmaxf(a1, qmax(A[c+4]));  b1 = fmaxf(b1, qmax(Bacc[c+4]));
  }
  out[((size_t)b*CC + lane)      * NN + nA] = a0;
  out[((size_t)b*CC + lane)      * NN + nB] = a1;
  out[((size_t)b*CC + lane + 32) * NN + nA] = b0;
  out[((size_t)b*CC + lane + 32) * NN + nB] = b1;
}

// ============================================================================
extern "C" void kernel_launch(void* const* d_in, const int* in_sizes, int n_in,
                              void* d_out, int out_size)
{
  const float* xyz = (const float*)d_in[0];
  const float* w1  = (const float*)d_in[1];
  const float* w2  = (const float*)d_in[2];
  const float* w3  = (const float*)d_in[3];
  float* out = (float*)d_out;
  (void)in_sizes; (void)n_in; (void)out_size;

  size_t ksmem = (size_t)NN * sizeof(float4);   // 64KB
  cudaFuncSetAttribute(knn_warp, cudaFuncAttributeMaxDynamicSharedMemorySize, (int)ksmem);
  knn_warp<<<dim3(NN/(QPW*KWPB), BB), KWPB*32, ksmem>>>(xyz);

  size_t msmem = (size_t)(256 + 4096 + 4096 + MW*2048) * sizeof(float); // 99328 B
  cudaFuncSetAttribute(mlp_kernel, cudaFuncAttributeMaxDynamicSharedMemorySize, (int)msmem);
  mlp_kernel<<<(BB*NN)/(MW*2), MT, msmem>>>(xyz, w1, w2, w3, out);
}